// round 13
// baseline (speedup 1.0000x reference)
#include <cuda_runtime.h>
#include <cstdint>

#define TSTEPS 128
#define BATCH  1024
#define HID    512
#define G4     2048
#define FUTN   32

#define NCTA   128
#define NTHR   512          // 16 warps
#define KT     32           // K-chunk in floats
#define ROWB   144          // padded row stride in bytes (128B data + 16B pad)
#define TILE_B (128 * ROWB) // 18432 B per operand tile
#define STG_B  (2 * TILE_B) // A + B per stage
#define NSTG   4
#define SMEM_BYTES (NSTG * STG_B)   // 147456 B dynamic

enum { MODE_L1 = 0, MODE_FUTA = 1, MODE_L2 = 2, MODE_PRE = 3 };

// ---------------- device globals (static scratch) ----------------
__device__ float g_hcat[2][BATCH][1024];    // [buf][b][0:512]=h1, [512:1024]=h2
__device__ float g_c1[BATCH][HID];
__device__ float g_c2[BATCH][HID];
__device__ float g_W1r[G4][HID];            // Whh1 rows reordered r'=4j+gate, tf32-rounded
__device__ float g_W2cat[G4][1024];         // [Wih2r | Whh2r], tf32-rounded
__device__ float g_W1pad[G4][32];           // Wih1r in cols 0..3, zeros elsewhere
__device__ float g_xpad[TSTEPS][BATCH][32]; // x in cols 0..3 (tf32-rounded), zeros elsewhere
__device__ float g_b1r[G4];
__device__ float g_b2r[G4];
__device__ float g_prefut[BATCH][G4];
__device__ unsigned g_bar_cnt, g_bar_gen;
__device__ unsigned g_grp_cnt[8][32];       // one monotonic counter per row-group, 128B apart

// ---------------- helpers ----------------
__device__ __forceinline__ float tf32r(float x) {
    asm("cvt.rna.tf32.f32 %0, %1;" : "=f"(x) : "f"(x));
    return x;
}
__device__ __forceinline__ float sigm(float v) { return __fdividef(1.f, 1.f + __expf(-v)); }
__device__ __forceinline__ float tanh_f(float v) { return __fdividef(2.f, 1.f + __expf(-2.f * v)) - 1.f; }

__device__ __forceinline__ void cp16(uint32_t s, const float* g) {
    asm volatile("cp.async.cg.shared.global [%0], [%1], 16;" :: "r"(s), "l"(g));
}
#define CP_COMMIT() asm volatile("cp.async.commit_group;" ::)
#define CP_WAIT2()  asm volatile("cp.async.wait_group 2;" ::)
#define CP_WAIT1()  asm volatile("cp.async.wait_group 1;" ::)
#define CP_WAIT0()  asm volatile("cp.async.wait_group 0;" ::)

__device__ __forceinline__ void ldsm4(uint32_t* r, uint32_t a) {
    asm volatile("ldmatrix.sync.aligned.m8n8.x4.shared.b16 {%0,%1,%2,%3}, [%4];"
                 : "=r"(r[0]), "=r"(r[1]), "=r"(r[2]), "=r"(r[3]) : "r"(a));
}
__device__ __forceinline__ void mma8(float* c, const uint32_t* a, const uint32_t* b) {
    asm volatile(
        "mma.sync.aligned.m16n8k8.row.col.f32.tf32.tf32.f32 "
        "{%0,%1,%2,%3}, {%4,%5,%6,%7}, {%8,%9}, {%0,%1,%2,%3};\n"
        : "+f"(c[0]), "+f"(c[1]), "+f"(c[2]), "+f"(c[3])
        : "r"(a[0]), "r"(a[1]), "r"(a[2]), "r"(a[3]), "r"(b[0]), "r"(b[1]));
}

// Full grid barrier (init only).
__device__ __forceinline__ void grid_bar() {
    __threadfence();
    __syncthreads();
    if (threadIdx.x == 0) {
        unsigned gen = atomicAdd(&g_bar_gen, 0u);
        unsigned t = atomicAdd(&g_bar_cnt, 1u);
        if (t == NCTA - 1) {
            atomicExch(&g_bar_cnt, 0u);
            atomicAdd(&g_bar_gen, 1u);
        } else {
            while (atomicAdd(&g_bar_gen, 0u) == gen) { __nanosleep(64); }
        }
        __threadfence();
    }
    __syncthreads();
}

// Group barrier: 16 CTAs sharing a 128-row batch block. Monotonic counter,
// release-arrive + acquire-poll. No L1 flush: cross-CTA data (h) moves via
// cp.async.cg / __ldcg (L2-only); c-state/prefut are CTA-private.
__device__ __forceinline__ void group_bar(unsigned* ctr, unsigned target) {
    __syncthreads();
    if (threadIdx.x == 0) {
        asm volatile("red.release.gpu.global.add.u32 [%0], %1;" :: "l"(ctr), "r"(1u) : "memory");
        unsigned v;
        do {
            asm volatile("ld.acquire.gpu.global.u32 %0, [%1];" : "=r"(v) : "l"(ctr) : "memory");
        } while ((int)(v - target) < 0);
    }
    __syncthreads();
}

// ---------------- one GEMM phase + fused LSTM epilogue ----------------
// Tile: rows m0..m0+127 (batch block tm), cols c0..c0+127 (gate cols r'=4j+gate).
// D = A @ B^T over NK K-chunks of 32 floats. 16 warps, warp tile 32x32.
template <int MODE>
__device__ void gemm_phase(int t, int p, uint32_t smem_u,
                           float* __restrict__ hOut,    // row stride 1024 floats
                           float* __restrict__ cState)  // row stride 512 floats
{
    const int tid = threadIdx.x;
    const int m0 = (blockIdx.x >> 4) * 128;
    const int c0 = (blockIdx.x & 15) * 128;
    constexpr int NK = (MODE == MODE_L1) ? 17 : (MODE == MODE_L2) ? 32 : 16;

    const int lane = tid & 31, gid = lane >> 2, tig = lane & 3;
    const int warp = tid >> 5, wm = warp >> 2, wn = warp & 3;
    // A ldsm4 lane addressing (16 rows x 2 k-halves)
    const int rA = (lane & 7) + ((lane >> 3) & 1) * 8;
    const int cA = (lane >> 4) * 16;
    // B ldsm4 lane addressing (16 n-rows x 2 k-halves): lanes 0-7 rows 0-7 k-lo,
    // 8-15 rows 0-7 k-hi, 16-23 rows 8-15 k-lo, 24-31 rows 8-15 k-hi.
    const int rB4 = (lane & 7) + ((lane >> 4) << 3);
    const int cB4 = ((lane >> 3) & 1) * 16;

    float acc[2][4][4];
#pragma unroll
    for (int a = 0; a < 2; a++)
#pragma unroll
        for (int b = 0; b < 4; b++)
#pragma unroll
            for (int c = 0; c < 4; c++) acc[a][b][c] = 0.f;

    auto prefetch = [&](int c) {
        const float* As; const float* Bs; int Al, Bl;
        if (MODE == MODE_L1) {
            if (c < 16) { As = &g_hcat[p][m0][c * 32]; Al = 1024; Bs = &g_W1r[c0][c * 32]; Bl = 512; }
            else        { As = &g_xpad[t][m0][0];      Al = 32;   Bs = &g_W1pad[c0][0];    Bl = 32; }
        } else if (MODE == MODE_L2) {
            int k0 = c * 32;
            As = (k0 < 512) ? &g_hcat[1 - p][m0][k0] : &g_hcat[p][m0][k0];
            Al = 1024; Bs = &g_W2cat[c0][k0]; Bl = 1024;
        } else if (MODE == MODE_FUTA) {
            As = &g_hcat[p][m0][c * 32]; Al = 1024; Bs = &g_W2cat[c0][512 + c * 32]; Bl = 1024;
        } else { // PRE: A = frozen h2, B = Wih2r half
            As = &g_hcat[p][m0][512 + c * 32]; Al = 1024; Bs = &g_W2cat[c0][c * 32]; Bl = 1024;
        }
        uint32_t sa = smem_u + (c & (NSTG - 1)) * STG_B;
        uint32_t sb = sa + TILE_B;
#pragma unroll
        for (int i = 0; i < 2; i++) {
            int idx = i * NTHR + tid;
            int r = idx >> 3, kc = idx & 7;
            cp16(sa + r * ROWB + kc * 16, As + (size_t)r * Al + kc * 4);
            cp16(sb + r * ROWB + kc * 16, Bs + (size_t)r * Bl + kc * 4);
        }
        CP_COMMIT();
    };

    prefetch(0); prefetch(1); prefetch(2);

#pragma unroll 1
    for (int c = 0; c < NK; c++) {
        if (c + 3 <= NK) CP_WAIT2(); else if (c + 2 == NK) CP_WAIT1(); else CP_WAIT0();
        __syncthreads();                 // stage c ready; stage (c+3)&3 free to refill
        if (c + 3 < NK) prefetch(c + 3);

        const uint32_t sa = smem_u + (c & (NSTG - 1)) * STG_B;
        const uint32_t sb = sa + TILE_B;
#pragma unroll
        for (int k8 = 0; k8 < KT / 8; k8++) {
            uint32_t af[2][4], bf[4][2];
#pragma unroll
            for (int mt = 0; mt < 2; mt++)
                ldsm4(af[mt], sa + (wm * 32 + mt * 16 + rA) * ROWB + k8 * 32 + cA);
#pragma unroll
            for (int nt2 = 0; nt2 < 2; nt2++)   // one ldsm4 = B frags for two n-tiles
                ldsm4(&bf[2 * nt2][0], sb + (wn * 32 + nt2 * 16 + rB4) * ROWB + k8 * 32 + cB4);
#pragma unroll
            for (int mt = 0; mt < 2; mt++)
#pragma unroll
                for (int nt = 0; nt < 4; nt++) mma8(acc[mt][nt], af[mt], bf[nt]);
        }
    }

    // -------- epilogue: pre-terms --------
#pragma unroll
    for (int mt = 0; mt < 2; mt++) {
        int r0 = m0 + wm * 32 + mt * 16 + gid;
#pragma unroll
        for (int nt = 0; nt < 4; nt++) {
            int gc = c0 + wn * 32 + nt * 8 + 2 * tig;
            if (MODE == MODE_FUTA) {
                float2 p0 = *(const float2*)&g_prefut[r0][gc];
                float2 p1 = *(const float2*)&g_prefut[r0 + 8][gc];
                acc[mt][nt][0] += p0.x; acc[mt][nt][1] += p0.y;
                acc[mt][nt][2] += p1.x; acc[mt][nt][3] += p1.y;
            } else {
                const float* bb = (MODE == MODE_L1) ? g_b1r : g_b2r;
                float2 b = *(const float2*)&bb[gc];
                acc[mt][nt][0] += b.x; acc[mt][nt][1] += b.y;
                acc[mt][nt][2] += b.x; acc[mt][nt][3] += b.y;
            }
        }
    }

    if (MODE == MODE_PRE) {
#pragma unroll
        for (int mt = 0; mt < 2; mt++) {
            int r0 = m0 + wm * 32 + mt * 16 + gid;
#pragma unroll
            for (int nt = 0; nt < 4; nt++) {
                int gc = c0 + wn * 32 + nt * 8 + 2 * tig;
                *(float2*)&g_prefut[r0][gc]     = make_float2(acc[mt][nt][0], acc[mt][nt][1]);
                *(float2*)&g_prefut[r0 + 8][gc] = make_float2(acc[mt][nt][2], acc[mt][nt][3]);
            }
        }
        return;
    }

    // -------- epilogue: LSTM cell update (all 32 lanes active) --------
    // Columns are r'=4j+gate. Lane pair (tig, tig^1) handles hidden unit
    // j = base/4 + tig/2; even lane takes row r0, odd lane row r0+8.
    const bool odd = (tig & 1);
#pragma unroll
    for (int mt = 0; mt < 2; mt++) {
        int r0 = m0 + wm * 32 + mt * 16 + gid;
#pragma unroll
        for (int nt = 0; nt < 4; nt++) {
            float s0 = odd ? acc[mt][nt][0] : acc[mt][nt][2];
            float s1 = odd ? acc[mt][nt][1] : acc[mt][nt][3];
            float u0 = __shfl_xor_sync(0xffffffffu, s0, 1);
            float u1 = __shfl_xor_sync(0xffffffffu, s1, 1);
            float gi = odd ? u0 : acc[mt][nt][0];
            float gf = odd ? u1 : acc[mt][nt][1];
            float gg = odd ? acc[mt][nt][2] : u0;
            float go = odd ? acc[mt][nt][3] : u1;
            int row = odd ? (r0 + 8) : r0;
            int j = ((c0 + wn * 32 + nt * 8) >> 2) + (tig >> 1);
            float co = cState[(size_t)row * HID + j];
            float cn = sigm(gf) * co + sigm(gi) * tanh_f(gg);
            float hn = sigm(go) * tanh_f(cn);
            cState[(size_t)row * HID + j] = cn;
            hOut[(size_t)row * 1024 + j] = tf32r(hn);
        }
    }
}

// Per-CTA output GEMV: CTA (tm,tn) handles 8 batch rows of its own block.
__device__ void out_gemv(const float* __restrict__ h2, const float* __restrict__ Wl,
                         const float* __restrict__ bl, float* __restrict__ out, int t)
{
    const int tid = threadIdx.x;
    const int tm = blockIdx.x >> 4, tn = blockIdx.x & 15;
    const int oi = tid >> 4;           // 0..31: 8 rows x 4 outs
    const int sub = tid & 15;
    const int b = tm * 128 + tn * 8 + (oi >> 2);
    const int o = oi & 3;
    const float* hr = h2 + (size_t)b * 1024 + sub * 32;
    const float* wr = Wl + o * HID + sub * 32;
    float s = 0.f;
#pragma unroll
    for (int k = 0; k < 32; k += 4) {
        float4 hv = __ldcg((const float4*)(hr + k));
        float4 wv = *(const float4*)(wr + k);
        s += hv.x * wv.x + hv.y * wv.y + hv.z * wv.z + hv.w * wv.w;
    }
    s += __shfl_xor_sync(0xffffffffu, s, 8);
    s += __shfl_xor_sync(0xffffffffu, s, 4);
    s += __shfl_xor_sync(0xffffffffu, s, 2);
    s += __shfl_xor_sync(0xffffffffu, s, 1);
    if (sub == 0) out[((size_t)t * BATCH + b) * 4 + o] = s + bl[o];
}

__global__ void __launch_bounds__(NTHR, 1)
lstm_kernel(const float* __restrict__ x,
            const float* __restrict__ Wih1, const float* __restrict__ Whh1,
            const float* __restrict__ bih1, const float* __restrict__ bhh1,
            const float* __restrict__ Wih2, const float* __restrict__ Whh2,
            const float* __restrict__ bih2, const float* __restrict__ bhh2,
            const float* __restrict__ Wl, const float* __restrict__ bl,
            float* __restrict__ out)
{
    extern __shared__ __align__(128) char smem[];
    const uint32_t smem_u = (uint32_t)__cvta_generic_to_shared(smem);
    const int tid = threadIdx.x;
    const int gtid = blockIdx.x * NTHR + tid;
    const int nth = NCTA * NTHR;

    // ---- init scratch (deterministic every launch) ----
    for (int i = gtid; i < BATCH * 2048; i += nth) (&g_hcat[0][0][0])[i] = 0.f;
    for (int i = gtid; i < BATCH * HID; i += nth) { (&g_c1[0][0])[i] = 0.f; (&g_c2[0][0])[i] = 0.f; }
    for (int i = gtid; i < G4 * HID; i += nth) {
        int r = i >> 9, k = i & 511, j = r >> 2, g = r & 3;
        g_W1r[r][k] = tf32r(Whh1[(size_t)(g * 512 + j) * 512 + k]);
    }
    for (int i = gtid; i < G4 * 1024; i += nth) {
        int r = i >> 10, k = i & 1023, j = r >> 2, g = r & 3;
        float v = (k < 512) ? Wih2[(size_t)(g * 512 + j) * 512 + k]
                            : Whh2[(size_t)(g * 512 + j) * 512 + (k - 512)];
        g_W2cat[r][k] = tf32r(v);
    }
    for (int r = gtid; r < G4; r += nth) {
        int j = r >> 2, g = r & 3;
        g_b1r[r] = bih1[g * 512 + j] + bhh1[g * 512 + j];
        g_b2r[r] = bih2[g * 512 + j] + bhh2[g * 512 + j];
        const float* s = &Wih1[(size_t)(g * 512 + j) * 4];
        float4 v = make_float4(tf32r(s[0]), tf32r(s[1]), tf32r(s[2]), tf32r(s[3]));
        float4 z = make_float4(0.f, 0.f, 0.f, 0.f);
        float4* d = (float4*)&g_W1pad[r][0];
        d[0] = v;
#pragma unroll
        for (int q = 1; q < 8; q++) d[q] = z;
    }
    for (int rb = gtid; rb < TSTEPS * BATCH; rb += nth) {
        const float* s = x + (size_t)rb * 4;
        float4 v = make_float4(tf32r(s[0]), tf32r(s[1]), tf32r(s[2]), tf32r(s[3]));
        float4 z = make_float4(0.f, 0.f, 0.f, 0.f);
        float4* d = (float4*)(&g_xpad[0][0][0] + (size_t)rb * 32);
        d[0] = v;
#pragma unroll
        for (int q = 1; q < 8; q++) d[q] = z;
    }
    grid_bar();   // full fence: weights/x now safe to cache anywhere

    // ---- group barrier setup (monotonic across graph replays) ----
    unsigned* const grp_ctr = &g_grp_cnt[blockIdx.x >> 4][0];
    unsigned bar_base = 0;
    if (tid == 0) {
        asm volatile("ld.acquire.gpu.global.u32 %0, [%1];" : "=r"(bar_base) : "l"(grp_ctr) : "memory");
    }
    unsigned phn = 0;
#define GB() group_bar(grp_ctr, bar_base + 16u * (++phn))

    int p = 0;
    // ---- main sequence ----
    for (int t = 0; t < TSTEPS; t++) {
        gemm_phase<MODE_L1>(t, p, smem_u, &g_hcat[1 - p][0][0], &g_c1[0][0]);
        GB();
        gemm_phase<MODE_L2>(t, p, smem_u, &g_hcat[1 - p][0][512], &g_c2[0][0]);
        GB();
        p ^= 1;
    }

    // prefut = tmp_out @ Wih2r^T + b2r (tmp_out = frozen h2)
    gemm_phase<MODE_PRE>(0, p, smem_u, nullptr, nullptr);
    GB();

    // ---- future loop ----
    for (int s = 0; s < FUTN; s++) {
        gemm_phase<MODE_FUTA>(0, p, smem_u, &g_hcat[1 - p][0][0], &g_c1[0][0]);
        GB();
        gemm_phase<MODE_L2>(0, p, smem_u, &g_hcat[1 - p][0][512], &g_c2[0][0]);
        GB();
        out_gemv(&g_hcat[1 - p][0][512], Wl, bl, out, s);
        p ^= 1;
    }
#undef GB
}

extern "C" void kernel_launch(void* const* d_in, const int* in_sizes, int n_in,
                              void* d_out, int out_size)
{
    (void)in_sizes; (void)n_in; (void)out_size;
    cudaFuncSetAttribute(lstm_kernel, cudaFuncAttributeMaxDynamicSharedMemorySize, SMEM_BYTES);
    lstm_kernel<<<NCTA, NTHR, SMEM_BYTES>>>(
        (const float*)d_in[0],
        (const float*)d_in[1], (const float*)d_in[2],
        (const float*)d_in[3], (const float*)d_in[4],
        (const float*)d_in[5], (const float*)d_in[6],
        (const float*)d_in[7], (const float*)d_in[8],
        (const float*)d_in[9], (const float*)d_in[10],
        (float*)d_out);
}

// round 14
// speedup vs baseline: 1.7229x; 1.7229x over previous
#include <cuda_runtime.h>
#include <cstdint>

#define TSTEPS 128
#define BATCH  1024
#define HID    512
#define G4     2048
#define FUTN   32

#define NCTA   128
#define NTHR   512          // 16 warps
#define KT     32           // K-chunk in floats
#define ROWB   144          // padded row stride in bytes (128B data + 16B pad)
#define TILE_B (128 * ROWB) // 18432 B per operand tile
#define STG_B  (2 * TILE_B) // A + B per stage
#define NSTG   4
#define SMEM_BYTES (NSTG * STG_B)   // 147456 B dynamic

enum { MODE_L1 = 0, MODE_FUTA = 1, MODE_L2 = 2, MODE_PRE = 3 };

// ---------------- device globals (static scratch) ----------------
__device__ float g_hcat[2][BATCH][1024];    // [buf][b][0:512]=h1, [512:1024]=h2
__device__ float g_c1[BATCH][HID];
__device__ float g_c2[BATCH][HID];
__device__ float g_W1r[G4][HID];            // Whh1 rows reordered r'=4j+gate, tf32-rounded
__device__ float g_W2cat[G4][1024];         // [Wih2r | Whh2r], tf32-rounded
__device__ float g_W1pad[G4][32];           // Wih1r in cols 0..3, zeros elsewhere
__device__ float g_xpad[TSTEPS][BATCH][32]; // x in cols 0..3 (tf32-rounded), zeros elsewhere
__device__ float g_b1r[G4];
__device__ float g_b2r[G4];
__device__ float g_prefut[BATCH][G4];
__device__ unsigned g_bar_cnt, g_bar_gen;
__device__ unsigned g_grp_cnt[8][32];       // one monotonic counter per row-group, 128B apart

// ---------------- helpers ----------------
__device__ __forceinline__ float tf32r(float x) {
    asm("cvt.rna.tf32.f32 %0, %1;" : "=f"(x) : "f"(x));
    return x;
}
__device__ __forceinline__ float sigm(float v) { return __fdividef(1.f, 1.f + __expf(-v)); }
__device__ __forceinline__ float tanh_f(float v) { return __fdividef(2.f, 1.f + __expf(-2.f * v)) - 1.f; }

__device__ __forceinline__ void cp16(uint32_t s, const float* g) {
    asm volatile("cp.async.cg.shared.global [%0], [%1], 16;" :: "r"(s), "l"(g));
}
#define CP_COMMIT() asm volatile("cp.async.commit_group;" ::)
#define CP_WAIT2()  asm volatile("cp.async.wait_group 2;" ::)
#define CP_WAIT1()  asm volatile("cp.async.wait_group 1;" ::)
#define CP_WAIT0()  asm volatile("cp.async.wait_group 0;" ::)

__device__ __forceinline__ void ldsm4(uint32_t* r, uint32_t a) {
    asm volatile("ldmatrix.sync.aligned.m8n8.x4.shared.b16 {%0,%1,%2,%3}, [%4];"
                 : "=r"(r[0]), "=r"(r[1]), "=r"(r[2]), "=r"(r[3]) : "r"(a));
}
__device__ __forceinline__ void mma8(float* c, const uint32_t* a, const uint32_t* b) {
    asm volatile(
        "mma.sync.aligned.m16n8k8.row.col.f32.tf32.tf32.f32 "
        "{%0,%1,%2,%3}, {%4,%5,%6,%7}, {%8,%9}, {%0,%1,%2,%3};\n"
        : "+f"(c[0]), "+f"(c[1]), "+f"(c[2]), "+f"(c[3])
        : "r"(a[0]), "r"(a[1]), "r"(a[2]), "r"(a[3]), "r"(b[0]), "r"(b[1]));
}

// Full grid barrier (init only).
__device__ __forceinline__ void grid_bar() {
    __threadfence();
    __syncthreads();
    if (threadIdx.x == 0) {
        unsigned gen = atomicAdd(&g_bar_gen, 0u);
        unsigned t = atomicAdd(&g_bar_cnt, 1u);
        if (t == NCTA - 1) {
            atomicExch(&g_bar_cnt, 0u);
            atomicAdd(&g_bar_gen, 1u);
        } else {
            while (atomicAdd(&g_bar_gen, 0u) == gen) { __nanosleep(64); }
        }
        __threadfence();
    }
    __syncthreads();
}

// Group barrier: 16 CTAs sharing a 128-row batch block. Monotonic counter,
// release-arrive + acquire-poll. No L1 flush: cross-CTA data (h) moves via
// cp.async.cg / __ldcg (L2-only); c-state/prefut are CTA-private.
__device__ __forceinline__ void group_bar(unsigned* ctr, unsigned target) {
    __syncthreads();
    if (threadIdx.x == 0) {
        asm volatile("red.release.gpu.global.add.u32 [%0], %1;" :: "l"(ctr), "r"(1u) : "memory");
        unsigned v;
        do {
            asm volatile("ld.acquire.gpu.global.u32 %0, [%1];" : "=r"(v) : "l"(ctr) : "memory");
        } while ((int)(v - target) < 0);
    }
    __syncthreads();
}

// ---------------- one GEMM phase + fused LSTM epilogue ----------------
// Tile: rows m0..m0+127 (batch block tm), cols c0..c0+127 (gate cols r'=4j+gate).
// D = A @ B^T over NK K-chunks of 32 floats. 16 warps, warp tile 32x32.
// Accumulators and epilogue stay INSIDE this function, constant-indexed only
// (array-parameter passing demotes acc to local memory — the R9-R13 killer).
template <int MODE>
__device__ void gemm_phase(int t, int p, uint32_t smem_u,
                           float* __restrict__ hOut,    // row stride 1024 floats
                           float* __restrict__ cState)  // row stride 512 floats
{
    const int tid = threadIdx.x;
    const int m0 = (blockIdx.x >> 4) * 128;
    const int c0 = (blockIdx.x & 15) * 128;
    constexpr int NK = (MODE == MODE_L1) ? 17 : (MODE == MODE_L2) ? 32 : 16;

    const int lane = tid & 31, gid = lane >> 2, tig = lane & 3;
    const int warp = tid >> 5, wm = warp >> 2, wn = warp & 3;
    // A ldsm4 lane addressing (16 rows x 2 k-halves)
    const int rA = (lane & 7) + ((lane >> 3) & 1) * 8;
    const int cA = (lane >> 4) * 16;
    // B ldsm4 lane addressing (16 n-rows x 2 k-halves): lanes 0-7 rows 0-7 k-lo,
    // 8-15 rows 0-7 k-hi, 16-23 rows 8-15 k-lo, 24-31 rows 8-15 k-hi.
    // (Mapping verified on-silicon in R13: passed with identical rel_err.)
    const int rB4 = (lane & 7) + ((lane >> 4) << 3);
    const int cB4 = ((lane >> 3) & 1) * 16;

    float acc[2][4][4];
#pragma unroll
    for (int a = 0; a < 2; a++)
#pragma unroll
        for (int b = 0; b < 4; b++)
#pragma unroll
            for (int c = 0; c < 4; c++) acc[a][b][c] = 0.f;

    auto prefetch = [&](int c) {
        const float* As; const float* Bs; int Al, Bl;
        if (MODE == MODE_L1) {
            if (c < 16) { As = &g_hcat[p][m0][c * 32]; Al = 1024; Bs = &g_W1r[c0][c * 32]; Bl = 512; }
            else        { As = &g_xpad[t][m0][0];      Al = 32;   Bs = &g_W1pad[c0][0];    Bl = 32; }
        } else if (MODE == MODE_L2) {
            int k0 = c * 32;
            As = (k0 < 512) ? &g_hcat[1 - p][m0][k0] : &g_hcat[p][m0][k0];
            Al = 1024; Bs = &g_W2cat[c0][k0]; Bl = 1024;
        } else if (MODE == MODE_FUTA) {
            As = &g_hcat[p][m0][c * 32]; Al = 1024; Bs = &g_W2cat[c0][512 + c * 32]; Bl = 1024;
        } else { // PRE: A = frozen h2, B = Wih2r half
            As = &g_hcat[p][m0][512 + c * 32]; Al = 1024; Bs = &g_W2cat[c0][c * 32]; Bl = 1024;
        }
        uint32_t sa = smem_u + (c & (NSTG - 1)) * STG_B;
        uint32_t sb = sa + TILE_B;
#pragma unroll
        for (int i = 0; i < 2; i++) {
            int idx = i * NTHR + tid;
            int r = idx >> 3, kc = idx & 7;
            cp16(sa + r * ROWB + kc * 16, As + (size_t)r * Al + kc * 4);
            cp16(sb + r * ROWB + kc * 16, Bs + (size_t)r * Bl + kc * 4);
        }
        CP_COMMIT();
    };

    prefetch(0); prefetch(1); prefetch(2);

#pragma unroll 1
    for (int c = 0; c < NK; c++) {
        if (c + 3 <= NK) CP_WAIT2(); else if (c + 2 == NK) CP_WAIT1(); else CP_WAIT0();
        __syncthreads();                 // stage c ready; stage (c+3)&3 free to refill
        if (c + 3 < NK) prefetch(c + 3);

        const uint32_t sa = smem_u + (c & (NSTG - 1)) * STG_B;
        const uint32_t sb = sa + TILE_B;
#pragma unroll
        for (int k8 = 0; k8 < KT / 8; k8++) {
            uint32_t af[2][4], bf[4][2];
#pragma unroll
            for (int mt = 0; mt < 2; mt++)
                ldsm4(af[mt], sa + (wm * 32 + mt * 16 + rA) * ROWB + k8 * 32 + cA);
#pragma unroll
            for (int nt2 = 0; nt2 < 2; nt2++)   // one ldsm4 = B frags for two n-tiles
                ldsm4(&bf[2 * nt2][0], sb + (wn * 32 + nt2 * 16 + rB4) * ROWB + k8 * 32 + cB4);
#pragma unroll
            for (int mt = 0; mt < 2; mt++)
#pragma unroll
                for (int nt = 0; nt < 4; nt++) mma8(acc[mt][nt], af[mt], bf[nt]);
        }
    }

    // -------- epilogue: pre-terms --------
#pragma unroll
    for (int mt = 0; mt < 2; mt++) {
        int r0 = m0 + wm * 32 + mt * 16 + gid;
#pragma unroll
        for (int nt = 0; nt < 4; nt++) {
            int gc = c0 + wn * 32 + nt * 8 + 2 * tig;
            if (MODE == MODE_FUTA) {
                float2 p0 = *(const float2*)&g_prefut[r0][gc];
                float2 p1 = *(const float2*)&g_prefut[r0 + 8][gc];
                acc[mt][nt][0] += p0.x; acc[mt][nt][1] += p0.y;
                acc[mt][nt][2] += p1.x; acc[mt][nt][3] += p1.y;
            } else {
                const float* bb = (MODE == MODE_L1) ? g_b1r : g_b2r;
                float2 b = *(const float2*)&bb[gc];
                acc[mt][nt][0] += b.x; acc[mt][nt][1] += b.y;
                acc[mt][nt][2] += b.x; acc[mt][nt][3] += b.y;
            }
        }
    }

    if (MODE == MODE_PRE) {
#pragma unroll
        for (int mt = 0; mt < 2; mt++) {
            int r0 = m0 + wm * 32 + mt * 16 + gid;
#pragma unroll
            for (int nt = 0; nt < 4; nt++) {
                int gc = c0 + wn * 32 + nt * 8 + 2 * tig;
                *(float2*)&g_prefut[r0][gc]     = make_float2(acc[mt][nt][0], acc[mt][nt][1]);
                *(float2*)&g_prefut[r0 + 8][gc] = make_float2(acc[mt][nt][2], acc[mt][nt][3]);
            }
        }
        return;
    }

    // -------- epilogue: LSTM cell update (R8 structure, fast-math transcendentals) --------
    // Columns are r'=4j+gate. Even-tig lane holds (i,f); xor-1 partner holds (g,o).
#pragma unroll
    for (int mt = 0; mt < 2; mt++) {
        int r0 = m0 + wm * 32 + mt * 16 + gid;
#pragma unroll
        for (int nt = 0; nt < 4; nt++) {
            int gc = c0 + wn * 32 + nt * 8 + 2 * tig;
#pragma unroll
            for (int h = 0; h < 2; h++) {
                int row = r0 + 8 * h;
                float v0 = acc[mt][nt][2 * h];
                float v1 = acc[mt][nt][2 * h + 1];
                float q0 = __shfl_xor_sync(0xffffffffu, v0, 1);
                float q1 = __shfl_xor_sync(0xffffffffu, v1, 1);
                if ((tig & 1) == 0) {
                    int j = gc >> 2;
                    float co = cState[(size_t)row * HID + j];
                    float cn = sigm(v1) * co + sigm(v0) * tanh_f(q0);
                    float hn = sigm(q1) * tanh_f(cn);
                    cState[(size_t)row * HID + j] = cn;
                    hOut[(size_t)row * 1024 + j] = tf32r(hn);
                }
            }
        }
    }
}

// Per-CTA output GEMV: CTA (tm,tn) handles 8 batch rows of its own block.
__device__ void out_gemv(const float* __restrict__ h2, const float* __restrict__ Wl,
                         const float* __restrict__ bl, float* __restrict__ out, int t)
{
    const int tid = threadIdx.x;
    const int tm = blockIdx.x >> 4, tn = blockIdx.x & 15;
    const int oi = tid >> 4;           // 0..31: 8 rows x 4 outs
    const int sub = tid & 15;
    const int b = tm * 128 + tn * 8 + (oi >> 2);
    const int o = oi & 3;
    const float* hr = h2 + (size_t)b * 1024 + sub * 32;
    const float* wr = Wl + o * HID + sub * 32;
    float s = 0.f;
#pragma unroll
    for (int k = 0; k < 32; k += 4) {
        float4 hv = __ldcg((const float4*)(hr + k));
        float4 wv = *(const float4*)(wr + k);
        s += hv.x * wv.x + hv.y * wv.y + hv.z * wv.z + hv.w * wv.w;
    }
    s += __shfl_xor_sync(0xffffffffu, s, 8);
    s += __shfl_xor_sync(0xffffffffu, s, 4);
    s += __shfl_xor_sync(0xffffffffu, s, 2);
    s += __shfl_xor_sync(0xffffffffu, s, 1);
    if (sub == 0) out[((size_t)t * BATCH + b) * 4 + o] = s + bl[o];
}

__global__ void __launch_bounds__(NTHR, 1)
lstm_kernel(const float* __restrict__ x,
            const float* __restrict__ Wih1, const float* __restrict__ Whh1,
            const float* __restrict__ bih1, const float* __restrict__ bhh1,
            const float* __restrict__ Wih2, const float* __restrict__ Whh2,
            const float* __restrict__ bih2, const float* __restrict__ bhh2,
            const float* __restrict__ Wl, const float* __restrict__ bl,
            float* __restrict__ out)
{
    extern __shared__ __align__(128) char smem[];
    const uint32_t smem_u = (uint32_t)__cvta_generic_to_shared(smem);
    const int tid = threadIdx.x;
    const int gtid = blockIdx.x * NTHR + tid;
    const int nth = NCTA * NTHR;

    // ---- init scratch (deterministic every launch) ----
    for (int i = gtid; i < BATCH * 2048; i += nth) (&g_hcat[0][0][0])[i] = 0.f;
    for (int i = gtid; i < BATCH * HID; i += nth) { (&g_c1[0][0])[i] = 0.f; (&g_c2[0][0])[i] = 0.f; }
    for (int i = gtid; i < G4 * HID; i += nth) {
        int r = i >> 9, k = i & 511, j = r >> 2, g = r & 3;
        g_W1r[r][k] = tf32r(Whh1[(size_t)(g * 512 + j) * 512 + k]);
    }
    for (int i = gtid; i < G4 * 1024; i += nth) {
        int r = i >> 10, k = i & 1023, j = r >> 2, g = r & 3;
        float v = (k < 512) ? Wih2[(size_t)(g * 512 + j) * 512 + k]
                            : Whh2[(size_t)(g * 512 + j) * 512 + (k - 512)];
        g_W2cat[r][k] = tf32r(v);
    }
    for (int r = gtid; r < G4; r += nth) {
        int j = r >> 2, g = r & 3;
        g_b1r[r] = bih1[g * 512 + j] + bhh1[g * 512 + j];
        g_b2r[r] = bih2[g * 512 + j] + bhh2[g * 512 + j];
        const float* s = &Wih1[(size_t)(g * 512 + j) * 4];
        float4 v = make_float4(tf32r(s[0]), tf32r(s[1]), tf32r(s[2]), tf32r(s[3]));
        float4 z = make_float4(0.f, 0.f, 0.f, 0.f);
        float4* d = (float4*)&g_W1pad[r][0];
        d[0] = v;
#pragma unroll
        for (int q = 1; q < 8; q++) d[q] = z;
    }
    for (int rb = gtid; rb < TSTEPS * BATCH; rb += nth) {
        const float* s = x + (size_t)rb * 4;
        float4 v = make_float4(tf32r(s[0]), tf32r(s[1]), tf32r(s[2]), tf32r(s[3]));
        float4 z = make_float4(0.f, 0.f, 0.f, 0.f);
        float4* d = (float4*)(&g_xpad[0][0][0] + (size_t)rb * 32);
        d[0] = v;
#pragma unroll
        for (int q = 1; q < 8; q++) d[q] = z;
    }
    grid_bar();   // full fence: weights/x now safe to cache anywhere

    // ---- group barrier setup (monotonic across graph replays) ----
    unsigned* const grp_ctr = &g_grp_cnt[blockIdx.x >> 4][0];
    unsigned bar_base = 0;
    if (tid == 0) {
        asm volatile("ld.acquire.gpu.global.u32 %0, [%1];" : "=r"(bar_base) : "l"(grp_ctr) : "memory");
    }
    unsigned phn = 0;
#define GB() group_bar(grp_ctr, bar_base + 16u * (++phn))

    int p = 0;
    // ---- main sequence ----
    for (int t = 0; t < TSTEPS; t++) {
        gemm_phase<MODE_L1>(t, p, smem_u, &g_hcat[1 - p][0][0], &g_c1[0][0]);
        GB();
        gemm_phase<MODE_L2>(t, p, smem_u, &g_hcat[1 - p][0][512], &g_c2[0][0]);
        GB();
        p ^= 1;
    }

    // prefut = tmp_out @ Wih2r^T + b2r (tmp_out = frozen h2)
    gemm_phase<MODE_PRE>(0, p, smem_u, nullptr, nullptr);
    GB();

    // ---- future loop ----
    for (int s = 0; s < FUTN; s++) {
        gemm_phase<MODE_FUTA>(0, p, smem_u, &g_hcat[1 - p][0][0], &g_c1[0][0]);
        GB();
        gemm_phase<MODE_L2>(0, p, smem_u, &g_hcat[1 - p][0][512], &g_c2[0][0]);
        GB();
        out_gemv(&g_hcat[1 - p][0][512], Wl, bl, out, s);
        p ^= 1;
    }
#undef GB
}

extern "C" void kernel_launch(void* const* d_in, const int* in_sizes, int n_in,
                              void* d_out, int out_size)
{
    (void)in_sizes; (void)n_in; (void)out_size;
    cudaFuncSetAttribute(lstm_kernel, cudaFuncAttributeMaxDynamicSharedMemorySize, SMEM_BYTES);
    lstm_kernel<<<NCTA, NTHR, SMEM_BYTES>>>(
        (const float*)d_in[0],
        (const float*)d_in[1], (const float*)d_in[2],
        (const float*)d_in[3], (const float*)d_in[4],
        (const float*)d_in[5], (const float*)d_in[6],
        (const float*)d_in[7], (const float*)d_in[8],
        (const float*)d_in[9], (const float*)d_in[10],
        (float*)d_out);
}

// round 15
// speedup vs baseline: 1.7739x; 1.0296x over previous
#include <cuda_runtime.h>
#include <cstdint>

#define TSTEPS 128
#define BATCH  1024
#define HID    512
#define G4     2048
#define FUTN   32

#define NCTA   256
#define NTHR   256          // 8 warps; 2 CTAs per SM
#define KT     32           // K-chunk in floats
#define ROWB   144          // padded row stride in bytes (128B data + 16B pad)
#define A_TILE (64 * ROWB)  // 9216 B  (A: 64 rows)
#define B_TILE (128 * ROWB) // 18432 B (B: 128 rows)
#define STG_B  (A_TILE + B_TILE)
#define NSTG   4
#define SMEM_BYTES (NSTG * STG_B)   // 110592 B dynamic -> 2 CTAs/SM

enum { MODE_L1 = 0, MODE_FUTA = 1, MODE_L2 = 2, MODE_PRE = 3 };

// ---------------- device globals (static scratch) ----------------
__device__ float g_hcat[2][BATCH][1024];    // [buf][b][0:512]=h1, [512:1024]=h2
__device__ float g_c1[BATCH][HID];
__device__ float g_c2[BATCH][HID];
__device__ float g_W1r[G4][HID];            // Whh1 rows reordered r'=4j+gate, tf32-rounded
__device__ float g_W2cat[G4][1024];         // [Wih2r | Whh2r], tf32-rounded
__device__ float g_W1pad[G4][32];           // Wih1r in cols 0..3, zeros elsewhere
__device__ float g_xpad[TSTEPS][BATCH][32]; // x in cols 0..3 (tf32-rounded), zeros elsewhere
__device__ float g_b1r[G4];
__device__ float g_b2r[G4];
__device__ float g_prefut[BATCH][G4];
__device__ unsigned g_bar_cnt, g_bar_gen;
__device__ unsigned g_grp_cnt[16][32];      // one monotonic counter per 64-row group, 128B apart

// ---------------- helpers ----------------
__device__ __forceinline__ float tf32r(float x) {
    asm("cvt.rna.tf32.f32 %0, %1;" : "=f"(x) : "f"(x));
    return x;
}
__device__ __forceinline__ float sigm(float v) { return __fdividef(1.f, 1.f + __expf(-v)); }
__device__ __forceinline__ float tanh_f(float v) { return __fdividef(2.f, 1.f + __expf(-2.f * v)) - 1.f; }

__device__ __forceinline__ void cp16(uint32_t s, const float* g) {
    asm volatile("cp.async.cg.shared.global [%0], [%1], 16;" :: "r"(s), "l"(g));
}
#define CP_COMMIT() asm volatile("cp.async.commit_group;" ::)
#define CP_WAIT2()  asm volatile("cp.async.wait_group 2;" ::)
#define CP_WAIT1()  asm volatile("cp.async.wait_group 1;" ::)
#define CP_WAIT0()  asm volatile("cp.async.wait_group 0;" ::)

__device__ __forceinline__ void ldsm4(uint32_t* r, uint32_t a) {
    asm volatile("ldmatrix.sync.aligned.m8n8.x4.shared.b16 {%0,%1,%2,%3}, [%4];"
                 : "=r"(r[0]), "=r"(r[1]), "=r"(r[2]), "=r"(r[3]) : "r"(a));
}
__device__ __forceinline__ void mma8(float* c, const uint32_t* a, const uint32_t* b) {
    asm volatile(
        "mma.sync.aligned.m16n8k8.row.col.f32.tf32.tf32.f32 "
        "{%0,%1,%2,%3}, {%4,%5,%6,%7}, {%8,%9}, {%0,%1,%2,%3};\n"
        : "+f"(c[0]), "+f"(c[1]), "+f"(c[2]), "+f"(c[3])
        : "r"(a[0]), "r"(a[1]), "r"(a[2]), "r"(a[3]), "r"(b[0]), "r"(b[1]));
}

// Full grid barrier (init only). 256 CTAs, 2/SM, all resident (296 slots).
__device__ __forceinline__ void grid_bar() {
    __threadfence();
    __syncthreads();
    if (threadIdx.x == 0) {
        unsigned gen = atomicAdd(&g_bar_gen, 0u);
        unsigned t = atomicAdd(&g_bar_cnt, 1u);
        if (t == NCTA - 1) {
            atomicExch(&g_bar_cnt, 0u);
            atomicAdd(&g_bar_gen, 1u);
        } else {
            while (atomicAdd(&g_bar_gen, 0u) == gen) { __nanosleep(64); }
        }
        __threadfence();
    }
    __syncthreads();
}

// Group barrier: 16 CTAs sharing a 64-row batch block. Monotonic counter,
// release-arrive + acquire-poll. No L1 flush: cross-CTA data (h) moves via
// cp.async.cg / __ldcg (L2-only); c-state/prefut are CTA-private.
__device__ __forceinline__ void group_bar(unsigned* ctr, unsigned target) {
    __syncthreads();
    if (threadIdx.x == 0) {
        asm volatile("red.release.gpu.global.add.u32 [%0], %1;" :: "l"(ctr), "r"(1u) : "memory");
        unsigned v;
        do {
            asm volatile("ld.acquire.gpu.global.u32 %0, [%1];" : "=r"(v) : "l"(ctr) : "memory");
        } while ((int)(v - target) < 0);
    }
    __syncthreads();
}

// ---------------- one GEMM phase + fused LSTM epilogue ----------------
// Tile: rows m0..m0+63 (batch block tm), cols c0..c0+127 (gate cols r'=4j+gate).
// D = A @ B^T over NK K-chunks of 32 floats. 8 warps (2x4), warp tile 32x32.
// Accumulators and epilogue stay INSIDE this function, constant-indexed only
// (array-parameter passing demotes acc to local memory — the R9-R13 killer).
template <int MODE>
__device__ void gemm_phase(int t, int p, uint32_t smem_u,
                           float* __restrict__ hOut,    // row stride 1024 floats
                           float* __restrict__ cState)  // row stride 512 floats
{
    const int tid = threadIdx.x;
    const int m0 = (blockIdx.x >> 4) * 64;
    const int c0 = (blockIdx.x & 15) * 128;
    constexpr int NK = (MODE == MODE_L1) ? 17 : (MODE == MODE_L2) ? 32 : 16;

    const int lane = tid & 31, gid = lane >> 2, tig = lane & 3;
    const int warp = tid >> 5, wm = warp >> 2, wn = warp & 3;   // wm 0..1, wn 0..3
    // A ldsm4 lane addressing (16 rows x 2 k-halves)
    const int rA = (lane & 7) + ((lane >> 3) & 1) * 8;
    const int cA = (lane >> 4) * 16;
    // B ldsm4 lane addressing (16 n-rows x 2 k-halves) — verified on-silicon R13/R14
    const int rB4 = (lane & 7) + ((lane >> 4) << 3);
    const int cB4 = ((lane >> 3) & 1) * 16;

    float acc[2][4][4];
#pragma unroll
    for (int a = 0; a < 2; a++)
#pragma unroll
        for (int b = 0; b < 4; b++)
#pragma unroll
            for (int c = 0; c < 4; c++) acc[a][b][c] = 0.f;

    auto prefetch = [&](int c) {
        const float* As; const float* Bs; int Al, Bl;
        if (MODE == MODE_L1) {
            if (c < 16) { As = &g_hcat[p][m0][c * 32]; Al = 1024; Bs = &g_W1r[c0][c * 32]; Bl = 512; }
            else        { As = &g_xpad[t][m0][0];      Al = 32;   Bs = &g_W1pad[c0][0];    Bl = 32; }
        } else if (MODE == MODE_L2) {
            int k0 = c * 32;
            As = (k0 < 512) ? &g_hcat[1 - p][m0][k0] : &g_hcat[p][m0][k0];
            Al = 1024; Bs = &g_W2cat[c0][k0]; Bl = 1024;
        } else if (MODE == MODE_FUTA) {
            As = &g_hcat[p][m0][c * 32]; Al = 1024; Bs = &g_W2cat[c0][512 + c * 32]; Bl = 1024;
        } else { // PRE: A = frozen h2, B = Wih2r half
            As = &g_hcat[p][m0][512 + c * 32]; Al = 1024; Bs = &g_W2cat[c0][c * 32]; Bl = 1024;
        }
        uint32_t sa = smem_u + (c & (NSTG - 1)) * STG_B;
        uint32_t sb = sa + A_TILE;
#pragma unroll
        for (int i = 0; i < 2; i++) {             // A: 64 rows x 8 pieces = 512
            int idx = i * NTHR + tid;
            int r = idx >> 3, kc = idx & 7;
            cp16(sa + r * ROWB + kc * 16, As + (size_t)r * Al + kc * 4);
        }
#pragma unroll
        for (int i = 0; i < 4; i++) {             // B: 128 rows x 8 pieces = 1024
            int idx = i * NTHR + tid;
            int r = idx >> 3, kc = idx & 7;
            cp16(sb + r * ROWB + kc * 16, Bs + (size_t)r * Bl + kc * 4);
        }
        CP_COMMIT();
    };

    prefetch(0); prefetch(1); prefetch(2);

#pragma unroll 1
    for (int c = 0; c < NK; c++) {
        if (c + 3 <= NK) CP_WAIT2(); else if (c + 2 == NK) CP_WAIT1(); else CP_WAIT0();
        __syncthreads();                 // stage c ready; stage (c+3)&3 free to refill
        if (c + 3 < NK) prefetch(c + 3);

        const uint32_t sa = smem_u + (c & (NSTG - 1)) * STG_B;
        const uint32_t sb = sa + A_TILE;
#pragma unroll
        for (int k8 = 0; k8 < KT / 8; k8++) {
            uint32_t af[2][4], bf[4][2];
#pragma unroll
            for (int mt = 0; mt < 2; mt++)
                ldsm4(af[mt], sa + (wm * 32 + mt * 16 + rA) * ROWB + k8 * 32 + cA);
#pragma unroll
            for (int nt2 = 0; nt2 < 2; nt2++)   // one ldsm4 = B frags for two n-tiles
                ldsm4(&bf[2 * nt2][0], sb + (wn * 32 + nt2 * 16 + rB4) * ROWB + k8 * 32 + cB4);
#pragma unroll
            for (int mt = 0; mt < 2; mt++)
#pragma unroll
                for (int nt = 0; nt < 4; nt++) mma8(acc[mt][nt], af[mt], bf[nt]);
        }
    }

    // -------- epilogue: pre-terms --------
#pragma unroll
    for (int mt = 0; mt < 2; mt++) {
        int r0 = m0 + wm * 32 + mt * 16 + gid;
#pragma unroll
        for (int nt = 0; nt < 4; nt++) {
            int gc = c0 + wn * 32 + nt * 8 + 2 * tig;
            if (MODE == MODE_FUTA) {
                float2 p0 = *(const float2*)&g_prefut[r0][gc];
                float2 p1 = *(const float2*)&g_prefut[r0 + 8][gc];
                acc[mt][nt][0] += p0.x; acc[mt][nt][1] += p0.y;
                acc[mt][nt][2] += p1.x; acc[mt][nt][3] += p1.y;
            } else {
                const float* bb = (MODE == MODE_L1) ? g_b1r : g_b2r;
                float2 b = *(const float2*)&bb[gc];
                acc[mt][nt][0] += b.x; acc[mt][nt][1] += b.y;
                acc[mt][nt][2] += b.x; acc[mt][nt][3] += b.y;
            }
        }
    }

    if (MODE == MODE_PRE) {
#pragma unroll
        for (int mt = 0; mt < 2; mt++) {
            int r0 = m0 + wm * 32 + mt * 16 + gid;
#pragma unroll
            for (int nt = 0; nt < 4; nt++) {
                int gc = c0 + wn * 32 + nt * 8 + 2 * tig;
                *(float2*)&g_prefut[r0][gc]     = make_float2(acc[mt][nt][0], acc[mt][nt][1]);
                *(float2*)&g_prefut[r0 + 8][gc] = make_float2(acc[mt][nt][2], acc[mt][nt][3]);
            }
        }
        return;
    }

    // -------- epilogue: LSTM cell update --------
    // Columns are r'=4j+gate. Even-tig lane holds (i,f); xor-1 partner holds (g,o).
#pragma unroll
    for (int mt = 0; mt < 2; mt++) {
        int r0 = m0 + wm * 32 + mt * 16 + gid;
#pragma unroll
        for (int nt = 0; nt < 4; nt++) {
            int gc = c0 + wn * 32 + nt * 8 + 2 * tig;
#pragma unroll
            for (int h = 0; h < 2; h++) {
                int row = r0 + 8 * h;
                float v0 = acc[mt][nt][2 * h];
                float v1 = acc[mt][nt][2 * h + 1];
                float q0 = __shfl_xor_sync(0xffffffffu, v0, 1);
                float q1 = __shfl_xor_sync(0xffffffffu, v1, 1);
                if ((tig & 1) == 0) {
                    int j = gc >> 2;
                    float co = cState[(size_t)row * HID + j];
                    float cn = sigm(v1) * co + sigm(v0) * tanh_f(q0);
                    float hn = sigm(q1) * tanh_f(cn);
                    cState[(size_t)row * HID + j] = cn;
                    hOut[(size_t)row * 1024 + j] = tf32r(hn);
                }
            }
        }
    }
}

// Per-CTA output GEMV: CTA (tm,tn) handles 4 batch rows of its own 64-row block.
__device__ void out_gemv(const float* __restrict__ h2, const float* __restrict__ Wl,
                         const float* __restrict__ bl, float* __restrict__ out, int t)
{
    const int tid = threadIdx.x;
    const int tm = blockIdx.x >> 4, tn = blockIdx.x & 15;
    const int oi = tid >> 4;           // 0..15: 4 rows x 4 outs
    const int sub = tid & 15;
    const int b = tm * 64 + tn * 4 + (oi >> 2);
    const int o = oi & 3;
    const float* hr = h2 + (size_t)b * 1024 + sub * 32;
    const float* wr = Wl + o * HID + sub * 32;
    float s = 0.f;
#pragma unroll
    for (int k = 0; k < 32; k += 4) {
        float4 hv = __ldcg((const float4*)(hr + k));
        float4 wv = *(const float4*)(wr + k);
        s += hv.x * wv.x + hv.y * wv.y + hv.z * wv.z + hv.w * wv.w;
    }
    s += __shfl_xor_sync(0xffffffffu, s, 8);
    s += __shfl_xor_sync(0xffffffffu, s, 4);
    s += __shfl_xor_sync(0xffffffffu, s, 2);
    s += __shfl_xor_sync(0xffffffffu, s, 1);
    if (sub == 0) out[((size_t)t * BATCH + b) * 4 + o] = s + bl[o];
}

__global__ void __launch_bounds__(NTHR, 2)
lstm_kernel(const float* __restrict__ x,
            const float* __restrict__ Wih1, const float* __restrict__ Whh1,
            const float* __restrict__ bih1, const float* __restrict__ bhh1,
            const float* __restrict__ Wih2, const float* __restrict__ Whh2,
            const float* __restrict__ bih2, const float* __restrict__ bhh2,
            const float* __restrict__ Wl, const float* __restrict__ bl,
            float* __restrict__ out)
{
    extern __shared__ __align__(128) char smem[];
    const uint32_t smem_u = (uint32_t)__cvta_generic_to_shared(smem);
    const int tid = threadIdx.x;
    const int gtid = blockIdx.x * NTHR + tid;
    const int nth = NCTA * NTHR;

    // ---- init scratch (deterministic every launch) ----
    for (int i = gtid; i < BATCH * 2048; i += nth) (&g_hcat[0][0][0])[i] = 0.f;
    for (int i = gtid; i < BATCH * HID; i += nth) { (&g_c1[0][0])[i] = 0.f; (&g_c2[0][0])[i] = 0.f; }
    for (int i = gtid; i < G4 * HID; i += nth) {
        int r = i >> 9, k = i & 511, j = r >> 2, g = r & 3;
        g_W1r[r][k] = tf32r(Whh1[(size_t)(g * 512 + j) * 512 + k]);
    }
    for (int i = gtid; i < G4 * 1024; i += nth) {
        int r = i >> 10, k = i & 1023, j = r >> 2, g = r & 3;
        float v = (k < 512) ? Wih2[(size_t)(g * 512 + j) * 512 + k]
                            : Whh2[(size_t)(g * 512 + j) * 512 + (k - 512)];
        g_W2cat[r][k] = tf32r(v);
    }
    for (int r = gtid; r < G4; r += nth) {
        int j = r >> 2, g = r & 3;
        g_b1r[r] = bih1[g * 512 + j] + bhh1[g * 512 + j];
        g_b2r[r] = bih2[g * 512 + j] + bhh2[g * 512 + j];
        const float* s = &Wih1[(size_t)(g * 512 + j) * 4];
        float4 v = make_float4(tf32r(s[0]), tf32r(s[1]), tf32r(s[2]), tf32r(s[3]));
        float4 z = make_float4(0.f, 0.f, 0.f, 0.f);
        float4* d = (float4*)&g_W1pad[r][0];
        d[0] = v;
#pragma unroll
        for (int q = 1; q < 8; q++) d[q] = z;
    }
    for (int rb = gtid; rb < TSTEPS * BATCH; rb += nth) {
        const float* s = x + (size_t)rb * 4;
        float4 v = make_float4(tf32r(s[0]), tf32r(s[1]), tf32r(s[2]), tf32r(s[3]));
        float4 z = make_float4(0.f, 0.f, 0.f, 0.f);
        float4* d = (float4*)(&g_xpad[0][0][0] + (size_t)rb * 32);
        d[0] = v;
#pragma unroll
        for (int q = 1; q < 8; q++) d[q] = z;
    }
    grid_bar();   // full fence: weights/x now safe to cache anywhere

    // ---- group barrier setup (monotonic across graph replays) ----
    unsigned* const grp_ctr = &g_grp_cnt[blockIdx.x >> 4][0];
    unsigned bar_base = 0;
    if (tid == 0) {
        asm volatile("ld.acquire.gpu.global.u32 %0, [%1];" : "=r"(bar_base) : "l"(grp_ctr) : "memory");
    }
    unsigned phn = 0;
#define GB() group_bar(grp_ctr, bar_base + 16u * (++phn))

    int p = 0;
    // ---- main sequence ----
    for (int t = 0; t < TSTEPS; t++) {
        gemm_phase<MODE_L1>(t, p, smem_u, &g_hcat[1 - p][0][0], &g_c1[0][0]);
        GB();
        gemm_phase<MODE_L2>(t, p, smem_u, &g_hcat[1 - p][0][512], &g_c2[0][0]);
        GB();
        p ^= 1;
    }

    // prefut = tmp_out @ Wih2r^T + b2r (tmp_out = frozen h2)
    gemm_phase<MODE_PRE>(0, p, smem_u, nullptr, nullptr);
    GB();

    // ---- future loop ----
    for (int s = 0; s < FUTN; s++) {
        gemm_phase<MODE_FUTA>(0, p, smem_u, &g_hcat[1 - p][0][0], &g_c1[0][0]);
        GB();
        gemm_phase<MODE_L2>(0, p, smem_u, &g_hcat[1 - p][0][512], &g_c2[0][0]);
        GB();
        out_gemv(&g_hcat[1 - p][0][512], Wl, bl, out, s);
        p ^= 1;
    }
#undef GB
}

extern "C" void kernel_launch(void* const* d_in, const int* in_sizes, int n_in,
                              void* d_out, int out_size)
{
    (void)in_sizes; (void)n_in; (void)out_size;
    cudaFuncSetAttribute(lstm_kernel, cudaFuncAttributeMaxDynamicSharedMemorySize, SMEM_BYTES);
    lstm_kernel<<<NCTA, NTHR, SMEM_BYTES>>>(
        (const float*)d_in[0],
        (const float*)d_in[1], (const float*)d_in[2],
        (const float*)d_in[3], (const float*)d_in[4],
        (const float*)d_in[5], (const float*)d_in[6],
        (const float*)d_in[7], (const float*)d_in[8],
        (const float*)d_in[9], (const float*)d_in[10],
        (float*)d_out);
}

// round 16
// speedup vs baseline: 1.8000x; 1.0147x over previous
#include <cuda_runtime.h>
#include <cstdint>

#define TSTEPS 128
#define BATCH  1024
#define HID    512
#define G4     2048
#define FUTN   32

#define NCTA   256
#define NTHR   256          // 8 warps; 2 CTAs per SM
#define KT     64           // K-chunk in floats (256B rows)
#define ROWB   272          // padded row stride in bytes (256B data + 16B pad)
#define A_TILE (64 * ROWB)  // 17408 B (A: 64 rows)
#define B_TILE (128 * ROWB) // 34816 B (B: 128 rows)
#define STG_B  (A_TILE + B_TILE)
#define NSTG   2
#define SMEM_BYTES (NSTG * STG_B)   // 104448 B dynamic -> 2 CTAs/SM

enum { MODE_L1 = 0, MODE_FUTA = 1, MODE_L2 = 2, MODE_PRE = 3 };

// ---------------- device globals (static scratch) ----------------
__device__ float g_hcat[2][BATCH][1024];    // [buf][b][0:512]=h1, [512:1024]=h2
__device__ float g_c1[BATCH][HID];
__device__ float g_c2[BATCH][HID];
__device__ float g_W1r[G4][HID];            // Whh1 rows reordered r'=4j+gate, tf32-rounded
__device__ float g_W2cat[G4][1024];         // [Wih2r | Whh2r], tf32-rounded
__device__ float g_Wih1r[G4][4];            // Wih1 reordered (full fp32, epilogue FMA)
__device__ float g_b1r[G4];
__device__ float g_b2r[G4];
__device__ float g_prefut[BATCH][G4];
__device__ unsigned g_bar_cnt, g_bar_gen;
__device__ unsigned g_grp_cnt[16][32];      // one monotonic counter per 64-row group, 128B apart

// ---------------- helpers ----------------
__device__ __forceinline__ float tf32r(float x) {
    asm("cvt.rna.tf32.f32 %0, %1;" : "=f"(x) : "f"(x));
    return x;
}
__device__ __forceinline__ float sigm(float v) { return __fdividef(1.f, 1.f + __expf(-v)); }
__device__ __forceinline__ float tanh_f(float v) { return __fdividef(2.f, 1.f + __expf(-2.f * v)) - 1.f; }

__device__ __forceinline__ void cp16(uint32_t s, const float* g) {
    asm volatile("cp.async.cg.shared.global [%0], [%1], 16;" :: "r"(s), "l"(g));
}
#define CP_COMMIT() asm volatile("cp.async.commit_group;" ::)
#define CP_WAIT0()  asm volatile("cp.async.wait_group 0;" ::)

__device__ __forceinline__ void ldsm4(uint32_t* r, uint32_t a) {
    asm volatile("ldmatrix.sync.aligned.m8n8.x4.shared.b16 {%0,%1,%2,%3}, [%4];"
                 : "=r"(r[0]), "=r"(r[1]), "=r"(r[2]), "=r"(r[3]) : "r"(a));
}
__device__ __forceinline__ void mma8(float* c, const uint32_t* a, const uint32_t* b) {
    asm volatile(
        "mma.sync.aligned.m16n8k8.row.col.f32.tf32.tf32.f32 "
        "{%0,%1,%2,%3}, {%4,%5,%6,%7}, {%8,%9}, {%0,%1,%2,%3};\n"
        : "+f"(c[0]), "+f"(c[1]), "+f"(c[2]), "+f"(c[3])
        : "r"(a[0]), "r"(a[1]), "r"(a[2]), "r"(a[3]), "r"(b[0]), "r"(b[1]));
}

// Full grid barrier (init only). 256 CTAs, 2/SM, all resident.
__device__ __forceinline__ void grid_bar() {
    __threadfence();
    __syncthreads();
    if (threadIdx.x == 0) {
        unsigned gen = atomicAdd(&g_bar_gen, 0u);
        unsigned t = atomicAdd(&g_bar_cnt, 1u);
        if (t == NCTA - 1) {
            atomicExch(&g_bar_cnt, 0u);
            atomicAdd(&g_bar_gen, 1u);
        } else {
            while (atomicAdd(&g_bar_gen, 0u) == gen) { __nanosleep(64); }
        }
        __threadfence();
    }
    __syncthreads();
}

// Group barrier: 16 CTAs sharing a 64-row batch block. Monotonic counter,
// release-arrive + acquire-poll. No L1 flush: cross-CTA data (h) moves via
// cp.async.cg / __ldcg (L2-only); c-state/prefut are CTA-private.
__device__ __forceinline__ void group_bar(unsigned* ctr, unsigned target) {
    __syncthreads();
    if (threadIdx.x == 0) {
        asm volatile("red.release.gpu.global.add.u32 [%0], %1;" :: "l"(ctr), "r"(1u) : "memory");
        unsigned v;
        do {
            asm volatile("ld.acquire.gpu.global.u32 %0, [%1];" : "=r"(v) : "l"(ctr) : "memory");
        } while ((int)(v - target) < 0);
    }
    __syncthreads();
}

// ---------------- one GEMM phase + fused LSTM epilogue ----------------
// Tile: rows m0..m0+63 (batch block tm), cols c0..c0+127 (gate cols r'=4j+gate).
// D = A @ B^T over NK K-chunks of 64 floats. 8 warps (2x4), warp tile 32x32.
// Accumulators and epilogue stay INSIDE this function, constant-indexed only
// (array-parameter passing demotes acc to local memory — the R9-R13 killer).
template <int MODE>
__device__ void gemm_phase(int t, int p, uint32_t smem_u,
                           const float* __restrict__ x,
                           float* __restrict__ hOut,    // row stride 1024 floats
                           float* __restrict__ cState)  // row stride 512 floats
{
    const int tid = threadIdx.x;
    const int m0 = (blockIdx.x >> 4) * 64;
    const int c0 = (blockIdx.x & 15) * 128;
    constexpr int NK = (MODE == MODE_L2) ? 16 : 8;

    const int lane = tid & 31, gid = lane >> 2, tig = lane & 3;
    const int warp = tid >> 5, wm = warp >> 2, wn = warp & 3;   // wm 0..1, wn 0..3
    // A ldsm4 lane addressing (16 rows x 2 k-halves)
    const int rA = (lane & 7) + ((lane >> 3) & 1) * 8;
    const int cA = (lane >> 4) * 16;
    // B ldsm4 lane addressing (16 n-rows x 2 k-halves) — verified on-silicon R13-R15
    const int rB4 = (lane & 7) + ((lane >> 4) << 3);
    const int cB4 = ((lane >> 3) & 1) * 16;

    float acc[2][4][4];
#pragma unroll
    for (int a = 0; a < 2; a++)
#pragma unroll
        for (int b = 0; b < 4; b++)
#pragma unroll
            for (int c = 0; c < 4; c++) acc[a][b][c] = 0.f;

    auto prefetch = [&](int c) {
        const float* As; const float* Bs; int Bl;
        if (MODE == MODE_L1) {
            As = &g_hcat[p][m0][c * KT]; Bs = &g_W1r[c0][c * KT]; Bl = 512;
        } else if (MODE == MODE_L2) {
            int k0 = c * KT;
            As = (k0 < 512) ? &g_hcat[1 - p][m0][k0] : &g_hcat[p][m0][k0];
            Bs = &g_W2cat[c0][k0]; Bl = 1024;
        } else if (MODE == MODE_FUTA) {
            As = &g_hcat[p][m0][c * KT]; Bs = &g_W2cat[c0][512 + c * KT]; Bl = 1024;
        } else { // PRE: A = frozen h2, B = Wih2r half
            As = &g_hcat[p][m0][512 + c * KT]; Bs = &g_W2cat[c0][c * KT]; Bl = 1024;
        }
        uint32_t sa = smem_u + (c & (NSTG - 1)) * STG_B;
        uint32_t sb = sa + A_TILE;
#pragma unroll
        for (int i = 0; i < 4; i++) {             // A: 64 rows x 16 pieces = 1024
            int idx = i * NTHR + tid;
            int r = idx >> 4, kc = idx & 15;
            cp16(sa + r * ROWB + kc * 16, As + (size_t)r * 1024 + kc * 4);
        }
#pragma unroll
        for (int i = 0; i < 8; i++) {             // B: 128 rows x 16 pieces = 2048
            int idx = i * NTHR + tid;
            int r = idx >> 4, kc = idx & 15;
            cp16(sb + r * ROWB + kc * 16, Bs + (size_t)r * Bl + kc * 4);
        }
        CP_COMMIT();
    };

    prefetch(0);

#pragma unroll 1
    for (int c = 0; c < NK; c++) {
        CP_WAIT0();                       // chunk c landed (had compute(c-1) to fly)
        __syncthreads();                  // all warps done reading stage (c+1)&1
        if (c + 1 < NK) prefetch(c + 1);  // refill the other stage

        const uint32_t sa = smem_u + (c & (NSTG - 1)) * STG_B;
        const uint32_t sb = sa + A_TILE;
#pragma unroll
        for (int k8 = 0; k8 < KT / 8; k8++) {
            uint32_t af[2][4], bf[4][2];
#pragma unroll
            for (int mt = 0; mt < 2; mt++)
                ldsm4(af[mt], sa + (wm * 32 + mt * 16 + rA) * ROWB + k8 * 32 + cA);
#pragma unroll
            for (int nt2 = 0; nt2 < 2; nt2++)   // one ldsm4 = B frags for two n-tiles
                ldsm4(&bf[2 * nt2][0], sb + (wn * 32 + nt2 * 16 + rB4) * ROWB + k8 * 32 + cB4);
#pragma unroll
            for (int mt = 0; mt < 2; mt++)
#pragma unroll
                for (int nt = 0; nt < 4; nt++) mma8(acc[mt][nt], af[mt], bf[nt]);
        }
    }

    // -------- epilogue: pre-terms --------
#pragma unroll
    for (int mt = 0; mt < 2; mt++) {
        int r0 = m0 + wm * 32 + mt * 16 + gid;
        float4 x0, x1;
        if (MODE == MODE_L1) {
            x0 = *(const float4*)(x + ((size_t)t * BATCH + r0) * 4);
            x1 = *(const float4*)(x + ((size_t)t * BATCH + r0 + 8) * 4);
        }
#pragma unroll
        for (int nt = 0; nt < 4; nt++) {
            int gc = c0 + wn * 32 + nt * 8 + 2 * tig;
            if (MODE == MODE_L1) {
                float2 b = *(const float2*)&g_b1r[gc];
                float4 w0 = *(const float4*)&g_Wih1r[gc][0];
                float4 w1 = *(const float4*)&g_Wih1r[gc + 1][0];
                acc[mt][nt][0] += b.x + x0.x * w0.x + x0.y * w0.y + x0.z * w0.z + x0.w * w0.w;
                acc[mt][nt][1] += b.y + x0.x * w1.x + x0.y * w1.y + x0.z * w1.z + x0.w * w1.w;
                acc[mt][nt][2] += b.x + x1.x * w0.x + x1.y * w0.y + x1.z * w0.z + x1.w * w0.w;
                acc[mt][nt][3] += b.y + x1.x * w1.x + x1.y * w1.y + x1.z * w1.z + x1.w * w1.w;
            } else if (MODE == MODE_FUTA) {
                float2 p0 = *(const float2*)&g_prefut[r0][gc];
                float2 p1 = *(const float2*)&g_prefut[r0 + 8][gc];
                acc[mt][nt][0] += p0.x; acc[mt][nt][1] += p0.y;
                acc[mt][nt][2] += p1.x; acc[mt][nt][3] += p1.y;
            } else { // L2 / PRE
                float2 b = *(const float2*)&g_b2r[gc];
                acc[mt][nt][0] += b.x; acc[mt][nt][1] += b.y;
                acc[mt][nt][2] += b.x; acc[mt][nt][3] += b.y;
            }
        }
    }

    if (MODE == MODE_PRE) {
#pragma unroll
        for (int mt = 0; mt < 2; mt++) {
            int r0 = m0 + wm * 32 + mt * 16 + gid;
#pragma unroll
            for (int nt = 0; nt < 4; nt++) {
                int gc = c0 + wn * 32 + nt * 8 + 2 * tig;
                *(float2*)&g_prefut[r0][gc]     = make_float2(acc[mt][nt][0], acc[mt][nt][1]);
                *(float2*)&g_prefut[r0 + 8][gc] = make_float2(acc[mt][nt][2], acc[mt][nt][3]);
            }
        }
        return;
    }

    // -------- epilogue: LSTM cell update --------
    // Columns are r'=4j+gate. Even-tig lane holds (i,f); xor-1 partner holds (g,o).
#pragma unroll
    for (int mt = 0; mt < 2; mt++) {
        int r0 = m0 + wm * 32 + mt * 16 + gid;
#pragma unroll
        for (int nt = 0; nt < 4; nt++) {
            int gc = c0 + wn * 32 + nt * 8 + 2 * tig;
#pragma unroll
            for (int h = 0; h < 2; h++) {
                int row = r0 + 8 * h;
                float v0 = acc[mt][nt][2 * h];
                float v1 = acc[mt][nt][2 * h + 1];
                float q0 = __shfl_xor_sync(0xffffffffu, v0, 1);
                float q1 = __shfl_xor_sync(0xffffffffu, v1, 1);
                if ((tig & 1) == 0) {
                    int j = gc >> 2;
                    float co = cState[(size_t)row * HID + j];
                    float cn = sigm(v1) * co + sigm(v0) * tanh_f(q0);
                    float hn = sigm(q1) * tanh_f(cn);
                    cState[(size_t)row * HID + j] = cn;
                    hOut[(size_t)row * 1024 + j] = tf32r(hn);
                }
            }
        }
    }
}

// Per-CTA output GEMV: CTA (tm,tn) handles 4 batch rows of its own 64-row block.
__device__ void out_gemv(const float* __restrict__ h2, const float* __restrict__ Wl,
                         const float* __restrict__ bl, float* __restrict__ out, int t)
{
    const int tid = threadIdx.x;
    const int tm = blockIdx.x >> 4, tn = blockIdx.x & 15;
    const int oi = tid >> 4;           // 0..15: 4 rows x 4 outs
    const int sub = tid & 15;
    const int b = tm * 64 + tn * 4 + (oi >> 2);
    const int o = oi & 3;
    const float* hr = h2 + (size_t)b * 1024 + sub * 32;
    const float* wr = Wl + o * HID + sub * 32;
    float s = 0.f;
#pragma unroll
    for (int k = 0; k < 32; k += 4) {
        float4 hv = __ldcg((const float4*)(hr + k));
        float4 wv = *(const float4*)(wr + k);
        s += hv.x * wv.x + hv.y * wv.y + hv.z * wv.z + hv.w * wv.w;
    }
    s += __shfl_xor_sync(0xffffffffu, s, 8);
    s += __shfl_xor_sync(0xffffffffu, s, 4);
    s += __shfl_xor_sync(0xffffffffu, s, 2);
    s += __shfl_xor_sync(0xffffffffu, s, 1);
    if (sub == 0) out[((size_t)t * BATCH + b) * 4 + o] = s + bl[o];
}

__global__ void __launch_bounds__(NTHR, 2)
lstm_kernel(const float* __restrict__ x,
            const float* __restrict__ Wih1, const float* __restrict__ Whh1,
            const float* __restrict__ bih1, const float* __restrict__ bhh1,
            const float* __restrict__ Wih2, const float* __restrict__ Whh2,
            const float* __restrict__ bih2, const float* __restrict__ bhh2,
            const float* __restrict__ Wl, const float* __restrict__ bl,
            float* __restrict__ out)
{
    extern __shared__ __align__(128) char smem[];
    const uint32_t smem_u = (uint32_t)__cvta_generic_to_shared(smem);
    const int tid = threadIdx.x;
    const int gtid = blockIdx.x * NTHR + tid;
    const int nth = NCTA * NTHR;

    // ---- init scratch (deterministic every launch) ----
    for (int i = gtid; i < BATCH * 2048; i += nth) (&g_hcat[0][0][0])[i] = 0.f;
    for (int i = gtid; i < BATCH * HID; i += nth) { (&g_c1[0][0])[i] = 0.f; (&g_c2[0][0])[i] = 0.f; }
    for (int i = gtid; i < G4 * HID; i += nth) {
        int r = i >> 9, k = i & 511, j = r >> 2, g = r & 3;
        g_W1r[r][k] = tf32r(Whh1[(size_t)(g * 512 + j) * 512 + k]);
    }
    for (int i = gtid; i < G4 * 1024; i += nth) {
        int r = i >> 10, k = i & 1023, j = r >> 2, g = r & 3;
        float v = (k < 512) ? Wih2[(size_t)(g * 512 + j) * 512 + k]
                            : Whh2[(size_t)(g * 512 + j) * 512 + (k - 512)];
        g_W2cat[r][k] = tf32r(v);
    }
    for (int r = gtid; r < G4; r += nth) {
        int j = r >> 2, g = r & 3;
        g_b1r[r] = bih1[g * 512 + j] + bhh1[g * 512 + j];
        g_b2r[r] = bih2[g * 512 + j] + bhh2[g * 512 + j];
        *(float4*)&g_Wih1r[r][0] = *(const float4*)&Wih1[(size_t)(g * 512 + j) * 4];
    }
    grid_bar();   // full fence: weights/x now safe to cache anywhere

    // ---- group barrier setup (monotonic across graph replays) ----
    unsigned* const grp_ctr = &g_grp_cnt[blockIdx.x >> 4][0];
    unsigned bar_base = 0;
    if (tid == 0) {
        asm volatile("ld.acquire.gpu.global.u32 %0, [%1];" : "=r"(bar_base) : "l"(grp_ctr) : "memory");
    }
    unsigned phn = 0;
#define GB() group_bar(grp_ctr, bar_base + 16u * (++phn))

    int p = 0;
    // ---- main sequence ----
    for (int t = 0; t < TSTEPS; t++) {
        gemm_phase<MODE_L1>(t, p, smem_u, x, &g_hcat[1 - p][0][0], &g_c1[0][0]);
        GB();
        gemm_phase<MODE_L2>(t, p, smem_u, x, &g_hcat[1 - p][0][512], &g_c2[0][0]);
        GB();
        p ^= 1;
    }

    // prefut = tmp_out @ Wih2r^T + b2r (tmp_out = frozen h2)
    gemm_phase<MODE_PRE>(0, p, smem_u, x, nullptr, nullptr);
    GB();

    // ---- future loop ----
    for (int s = 0; s < FUTN; s++) {
        gemm_phase<MODE_FUTA>(0, p, smem_u, x, &g_hcat[1 - p][0][0], &g_c1[0][0]);
        GB();
        gemm_phase<MODE_L2>(0, p, smem_u, x, &g_hcat[1 - p][0][512], &g_c2[0][0]);
        GB();
        out_gemv(&g_hcat[1 - p][0][512], Wl, bl, out, s);
        p ^= 1;
    }
#undef GB
}

extern "C" void kernel_launch(void* const* d_in, const int* in_sizes, int n_in,
                              void* d_out, int out_size)
{
    (void)in_sizes; (void)n_in; (void)out_size;
    cudaFuncSetAttribute(lstm_kernel, cudaFuncAttributeMaxDynamicSharedMemorySize, SMEM_BYTES);
    lstm_kernel<<<NCTA, NTHR, SMEM_BYTES>>>(
        (const float*)d_in[0],
        (const float*)d_in[1], (const float*)d_in[2],
        (const float*)d_in[3], (const float*)d_in[4],
        (const float*)d_in[5], (const float*)d_in[6],
        (const float*)d_in[7], (const float*)d_in[8],
        (const float*)d_in[9], (const float*)d_in[10],
        (float*)d_out);
}